// round 12
// baseline (speedup 1.0000x reference)
#include <cuda_runtime.h>
#include <math.h>
#include <stdint.h>

#define Bq 16
#define Tq 512
#define Eq 100
#define Hq 500
#define G4 2000
#define NT 32
#define NEGV (-10000.0f)

#define NBLK 128
#define RTHR 128
#define GRPSZ 32

// sred padded strides (floats)
#define SR_B 68
#define SR_KS 548

typedef unsigned long long ull;

// ---------------- device scratch ----------------
__device__ float g_xs[Tq * Bq * Eq];
__device__ float g_A0[2u * Tq * Bq * G4];
__device__ float g_A1[2u * Tq * Bq * G4];
__device__ float g_out0[Tq * Bq * 2 * Hq];
__device__ float g_out1[Tq * Bq * 2 * Hq];
__device__ float g_y[Tq * Bq * NT];
__device__ float g_hbuf[2 * 2 * Bq * 512];     // [d][pp][b][512]
__device__ float g_gold[Bq];
__device__ float g_Z[Bq];
// mailbox flags: [group(4)][member(32)] each on its own 128B line (32 uints)
__device__ unsigned g_flag[4 * 32 * 32];

// ---------------- helpers ----------------
__device__ __forceinline__ float sigm_f(float v) {
    return __fdividef(1.0f, 1.0f + __expf(-v));
}
__device__ __forceinline__ float tanh_f(float v) {
    return 1.0f - __fdividef(2.0f, __expf(2.0f * v) + 1.0f);
}
__device__ __forceinline__ ull fma2(ull a, ull b, ull c) {
    ull d;
    asm("fma.rn.f32x2 %0, %1, %2, %3;" : "=l"(d) : "l"(a), "l"(b), "l"(c));
    return d;
}
__device__ __forceinline__ ull pk2(float a, float b) {
    ull r;
    asm("mov.b64 %0, {%1, %2};" : "=l"(r) : "f"(a), "f"(b));
    return r;
}
__device__ __forceinline__ float2 up2(ull v) {
    float2 r;
    asm("mov.b64 {%0, %1}, %2;" : "=f"(r.x), "=f"(r.y) : "l"(v));
    return r;
}
__device__ __forceinline__ void st_release(unsigned* p, unsigned v) {
    asm volatile("st.release.gpu.global.u32 [%0], %1;" :: "l"(p), "r"(v) : "memory");
}
__device__ __forceinline__ unsigned ld_acquire(const unsigned* p) {
    unsigned v;
    asm volatile("ld.acquire.gpu.global.u32 %0, [%1];" : "=r"(v) : "l"(p) : "memory");
    return v;
}

__global__ void k_reset() {
    for (int i = threadIdx.x; i < 4 * 32 * 32; i += blockDim.x) g_flag[i] = 0u;
}

// ---------------- embedding ----------------
__global__ void k_embed(const int* __restrict__ x, const float* __restrict__ embw) {
    int idx = blockIdx.x * blockDim.x + threadIdx.x;
    if (idx >= Tq * Bq * Eq) return;
    int e = idx % Eq;
    int rb = idx / Eq;
    int b = rb % Bq;
    int t = rb / Bq;
    int row = x[b * Tq + t];
    g_xs[idx] = embw[(size_t)row * Eq + e];
}

// ---------------- tiled fp32 GEMM, FFMA2, double-buffered smem ----------------
__global__ __launch_bounds__(256) void k_gemm(int lay,
                                              const float* __restrict__ W,
                                              const float* __restrict__ b1,
                                              const float* __restrict__ b2) {
    const int M = Tq * Bq;
    const int N = G4;
    const int K = (lay == 0) ? Eq : (2 * Hq);
    const float* X = (lay == 0) ? g_xs : g_out0;
    float* C = (lay == 0) ? g_A0 : g_A1;

    __shared__ ull sXp[2][8][64];
    __shared__ ull sWp[2][8][64];

    int d = blockIdx.z;
    const float* Wd = W + (size_t)d * N * K;
    const float* b1d = b1 + (size_t)d * N;
    const float* b2d = b2 + (size_t)d * N;
    float* Cd = C + (size_t)d * M * N;

    int m0 = blockIdx.y * 64, n0 = blockIdx.x * 64;
    int tid = threadIdx.x;
    int lr = tid >> 2;
    int lc = (tid & 3) * 4;
    int tx = tid & 15, ty = tid >> 4;

    ull acc2[4][4];
#pragma unroll
    for (int i = 0; i < 4; i++)
#pragma unroll
        for (int j = 0; j < 4; j++) acc2[i][j] = 0ull;

    const int nt = (K + 15) / 16;

    float4 xv = make_float4(0.f, 0.f, 0.f, 0.f);
    float4 wv = make_float4(0.f, 0.f, 0.f, 0.f);
    if (lc < K) xv = *(const float4*)&X[(size_t)(m0 + lr) * K + lc];
    if (lc < K) wv = *(const float4*)&Wd[(size_t)(n0 + lr) * K + lc];
    sXp[0][(lc >> 1) + 0][lr] = pk2(xv.x, xv.y);
    sXp[0][(lc >> 1) + 1][lr] = pk2(xv.z, xv.w);
    sWp[0][(lc >> 1) + 0][lr] = pk2(wv.x, wv.y);
    sWp[0][(lc >> 1) + 1][lr] = pk2(wv.z, wv.w);
    __syncthreads();

    for (int ti = 0; ti < nt; ti++) {
        int cur = ti & 1;
        float4 xn = make_float4(0.f, 0.f, 0.f, 0.f);
        float4 wn = make_float4(0.f, 0.f, 0.f, 0.f);
        if (ti + 1 < nt) {
            int kt = (ti + 1) * 16;
            if (kt + lc < K) xn = *(const float4*)&X[(size_t)(m0 + lr) * K + kt + lc];
            if (kt + lc < K) wn = *(const float4*)&Wd[(size_t)(n0 + lr) * K + kt + lc];
        }
#pragma unroll
        for (int kp = 0; kp < 8; kp++) {
            ulonglong2 xa = *(const ulonglong2*)&sXp[cur][kp][ty * 4 + 0];
            ulonglong2 xb = *(const ulonglong2*)&sXp[cur][kp][ty * 4 + 2];
            ulonglong2 wa = *(const ulonglong2*)&sWp[cur][kp][tx * 4 + 0];
            ulonglong2 wb = *(const ulonglong2*)&sWp[cur][kp][tx * 4 + 2];
            ull xp[4] = {xa.x, xa.y, xb.x, xb.y};
            ull wp[4] = {wa.x, wa.y, wb.x, wb.y};
#pragma unroll
            for (int i = 0; i < 4; i++)
#pragma unroll
                for (int j = 0; j < 4; j++)
                    acc2[i][j] = fma2(xp[i], wp[j], acc2[i][j]);
        }
        if (ti + 1 < nt) {
            int nxt = (ti + 1) & 1;
            sXp[nxt][(lc >> 1) + 0][lr] = pk2(xn.x, xn.y);
            sXp[nxt][(lc >> 1) + 1][lr] = pk2(xn.z, xn.w);
            sWp[nxt][(lc >> 1) + 0][lr] = pk2(wn.x, wn.y);
            sWp[nxt][(lc >> 1) + 1][lr] = pk2(wn.z, wn.w);
            __syncthreads();
        }
    }

#pragma unroll
    for (int i = 0; i < 4; i++) {
        int row = m0 + ty * 4 + i;
#pragma unroll
        for (int j = 0; j < 4; j++) {
            int col = n0 + tx * 4 + j;
            if (col < N) {
                float2 p = up2(acc2[i][j]);
                Cd[(size_t)row * N + col] = p.x + p.y + b1d[col] + b2d[col];
            }
        }
    }
}

// ---------------- persistent bidirectional LSTM, register-tiled ----------------
// 128 blocks = (2 dirs) x (2 b-groups of 8) x (32 j-groups of 16).
// 128 threads = 8 K-splits x (2 b-subgroups x 8 j-subgroups).
// Sync: per-block mailbox lines; warp0 lane L polls peer L's line. No shared hot line.
__device__ __forceinline__ void gbar_mb(unsigned* grpflags, int member, unsigned want) {
    __syncthreads();
    if (threadIdx.x < GRPSZ) {
        if (threadIdx.x == 0)
            st_release(grpflags + member * 32, want);
        const unsigned* p = grpflags + threadIdx.x * 32;
        unsigned ns = 20;
        while (ld_acquire(p) < want) {
            __nanosleep(ns);
            if (ns < 80) ns += ns;
        }
    }
    __syncthreads();
}

__global__ __launch_bounds__(RTHR, 1) void k_lstm(int lay,
                                                  const float* __restrict__ Whh,
                                                  const float* __restrict__ h0,
                                                  const float* __restrict__ c0,
                                                  const int* __restrict__ x) {
    extern __shared__ float sm[];
    float* sW = sm;            // [g][jl][i] : 4*16*500 = 32000 floats (128 KB)
    float* sh = sm + 32000;    // [bl][i]    : 8*500    = 4000 floats  (16 KB)
    float* sred = sm + 36000;  // [ks][b][j][g] padded : 8*548 = 4384 floats

    const float* A = (lay == 0) ? g_A0 : g_A1;
    float* outp = (lay == 0) ? g_out0 : g_out1;
    const int hbase = lay * 2;

    int tid = threadIdx.x;
    // dot role
    int ks = tid >> 4;          // 0..7
    int cell = tid & 15;
    int bg_t = cell & 1;        // 0..1 : batches bg_t*4 .. +3
    int jg_t = cell >> 1;       // 0..7 : j pair jg_t*2, jg_t*2+1
    // owner role
    int obl = tid & 7;          // batch 0..7
    int ojl = tid >> 3;         // j 0..15

    int bx = blockIdx.x;
    int d = bx >> 6;
    int rem = bx & 63;
    int bg = rem >> 5;
    int jg = rem & 31;          // group-local member id
    int b0 = bg * 8;
    int j0 = jg * 16;
    int oj = j0 + ojl;
    int ob = b0 + obl;
    bool jok = (oj < Hq);
    unsigned* grpflags = &g_flag[(d * 2 + bg) * 32 * 32];

    // load Whh slice: sW[(g*16+jl2)*500 + i]
    for (int idx = tid; idx < 32000; idx += RTHR) {
        int g = idx / 8000;
        int r = idx % 8000;
        int jl2 = r / 500;
        int i = r % 500;
        int jc = j0 + jl2;
        sW[idx] = (jc < Hq) ? Whh[((size_t)d * G4 + g * Hq + jc) * Hq + i] : 0.0f;
    }

    float hreg = jok ? h0[((size_t)(hbase + d) * Bq + ob) * Hq + oj] : 0.0f;
    float creg = jok ? c0[((size_t)(hbase + d) * Bq + ob) * Hq + oj] : 0.0f;
    g_hbuf[((d * 2 + 0) * Bq + ob) * 512 + oj] = hreg;
    unsigned bs = 1;
    gbar_mb(grpflags, jg, bs); bs++;

    const float* Ad = A + (size_t)d * Tq * Bq * G4;

    // K-slice for this thread: chunks of 4 floats (ulonglong2), 125 total
    int cb = ks * 15 + (ks < 5 ? ks : 5);
    int cn = (ks < 5) ? 16 : 15;

    // smem row pointers
    const ulonglong2* hrow[4];
#pragma unroll
    for (int bi = 0; bi < 4; bi++)
        hrow[bi] = (const ulonglong2*)&sh[(bg_t * 4 + bi) * 500];
    const ulonglong2* wrow[2][4];
#pragma unroll
    for (int ji = 0; ji < 2; ji++)
#pragma unroll
        for (int g = 0; g < 4; g++)
            wrow[ji][g] = (const ulonglong2*)&sW[(g * 16 + jg_t * 2 + ji) * 500];

    // A-prefetch for step 0
    float ag0, ag1, ag2, ag3;
    int xv;
    {
        int t0 = d ? (Tq - 1) : 0;
        size_t arow = ((size_t)t0 * Bq + ob) * G4 + (jok ? oj : 0);
        ag0 = __ldg(&Ad[arow + 0 * Hq]);
        ag1 = __ldg(&Ad[arow + 1 * Hq]);
        ag2 = __ldg(&Ad[arow + 2 * Hq]);
        ag3 = __ldg(&Ad[arow + 3 * Hq]);
        xv = __ldg(&x[ob * Tq + t0]);
    }

    int pp = 0;
    for (int s = 0; s < Tq; s++) {
        int t = d ? (Tq - 1 - s) : s;

        // stage h for this block's 8 batch rows: exactly 8*125 = 1000 float4
        for (int q = tid; q < 1000; q += RTHR) {
            int bb = q / 125;
            int i4 = q - bb * 125;
            float4 v = __ldcg((const float4*)&g_hbuf[((d * 2 + pp) * Bq + b0 + bb) * 512 + i4 * 4]);
            *(float4*)&sh[bb * 500 + i4 * 4] = v;
        }
        __syncthreads();

        // prefetch NEXT step's gate pre-activations + mask (hidden under the dot)
        float ng0 = 0.f, ng1 = 0.f, ng2 = 0.f, ng3 = 0.f;
        int nxv = 0;
        if (s + 1 < Tq) {
            int tn = d ? (Tq - 2 - s) : (s + 1);
            size_t arown = ((size_t)tn * Bq + ob) * G4 + (jok ? oj : 0);
            ng0 = __ldg(&Ad[arown + 0 * Hq]);
            ng1 = __ldg(&Ad[arown + 1 * Hq]);
            ng2 = __ldg(&Ad[arown + 2 * Hq]);
            ng3 = __ldg(&Ad[arown + 3 * Hq]);
            nxv = __ldg(&x[ob * Tq + tn]);
        }

        // register-tiled dot: acc[bi][ji][g]
        ull acc[4][2][4];
#pragma unroll
        for (int bi = 0; bi < 4; bi++)
#pragma unroll
            for (int ji = 0; ji < 2; ji++)
#pragma unroll
                for (int g = 0; g < 4; g++) acc[bi][ji][g] = 0ull;

#pragma unroll 2
        for (int ii = cb; ii < cb + cn; ii++) {
            ulonglong2 hv[4];
#pragma unroll
            for (int bi = 0; bi < 4; bi++) hv[bi] = hrow[bi][ii];
            ulonglong2 wv[2][4];
#pragma unroll
            for (int ji = 0; ji < 2; ji++)
#pragma unroll
                for (int g = 0; g < 4; g++) wv[ji][g] = wrow[ji][g][ii];
#pragma unroll
            for (int bi = 0; bi < 4; bi++)
#pragma unroll
                for (int ji = 0; ji < 2; ji++)
#pragma unroll
                    for (int g = 0; g < 4; g++) {
                        acc[bi][ji][g] = fma2(hv[bi].x, wv[ji][g].x, acc[bi][ji][g]);
                        acc[bi][ji][g] = fma2(hv[bi].y, wv[ji][g].y, acc[bi][ji][g]);
                    }
        }

        // write partials to sred[ks][b][j][g] (padded)
#pragma unroll
        for (int bi = 0; bi < 4; bi++)
#pragma unroll
            for (int ji = 0; ji < 2; ji++)
#pragma unroll
                for (int g = 0; g < 4; g++) {
                    float2 p = up2(acc[bi][ji][g]);
                    sred[ks * SR_KS + (bg_t * 4 + bi) * SR_B + (jg_t * 2 + ji) * 4 + g] = p.x + p.y;
                }
        __syncthreads();

        // owner: reduce 8 K-partials per gate, nonlinearity, state update
        {
            int base = obl * SR_B + ojl * 4;
            float gi = ag0, gf = ag1, gg = ag2, go = ag3;
#pragma unroll
            for (int k = 0; k < 8; k++) {
                const float* r = &sred[k * SR_KS + base];
                gi += r[0]; gf += r[1]; gg += r[2]; go += r[3];
            }

            float cn2 = sigm_f(gf) * creg + sigm_f(gi) * tanh_f(gg);
            float hn = sigm_f(go) * tanh_f(cn2);

            bool m = xv > 0;
            if (jok)
                outp[((size_t)t * Bq + ob) * (2 * Hq) + d * Hq + oj] = m ? hn : 0.0f;
            if (m) { creg = cn2; hreg = hn; }

            g_hbuf[((d * 2 + (pp ^ 1)) * Bq + ob) * 512 + oj] = hreg;
        }
        gbar_mb(grpflags, jg, bs); bs++;
        pp ^= 1;
        ag0 = ng0; ag1 = ng1; ag2 = ng2; ag3 = ng3; xv = nxv;
    }
}

// ---------------- output projection ----------------
__global__ __launch_bounds__(256) void k_outproj(const float* __restrict__ Wo,
                                                 const float* __restrict__ bo) {
    int r0 = blockIdx.x * 8;
    int tag = threadIdx.x & 31;
    int part = threadIdx.x >> 5;
    float acc[8];
#pragma unroll
    for (int r = 0; r < 8; r++) acc[r] = 0.0f;

    const float* w = Wo + (size_t)tag * 1000 + part * 125;
    for (int i = 0; i < 125; i++) {
        float wv = __ldg(&w[i]);
        int col = part * 125 + i;
#pragma unroll
        for (int r = 0; r < 8; r++)
            acc[r] = fmaf(wv, g_out1[(size_t)(r0 + r) * 1000 + col], acc[r]);
    }

    __shared__ float red[8][8][32];
#pragma unroll
    for (int r = 0; r < 8; r++) red[part][r][tag] = acc[r];
    __syncthreads();
    if (part == 0) {
#pragma unroll
        for (int r = 0; r < 8; r++) {
            float s = bo[tag];
#pragma unroll
            for (int p = 0; p < 8; p++) s += red[p][r][tag];
            g_y[(size_t)(r0 + r) * NT + tag] = s;
        }
    }
}

// ---------------- gold path score ----------------
__global__ void k_gold(const int* __restrict__ x, const int* __restrict__ y0,
                       const float* __restrict__ trans) {
    int b = blockIdx.x;
    float s = 0.0f;
    for (int t = threadIdx.x; t < Tq; t += blockDim.x) {
        if (x[b * Tq + t] > 0) {
            int cur = y0[b * Tq + t];
            int prev = (t == 0) ? 1 : y0[b * Tq + t - 1];
            s += g_y[((size_t)t * Bq + b) * NT + cur] + trans[cur * NT + prev];
        }
    }
    __shared__ float red[256];
    red[threadIdx.x] = s;
    __syncthreads();
    for (int k = 128; k > 0; k >>= 1) {
        if (threadIdx.x < k) red[threadIdx.x] += red[threadIdx.x + k];
        __syncthreads();
    }
    if (threadIdx.x == 0) g_gold[b] = red[0];
}

// ---------------- CRF forward ----------------
__global__ void k_crf(const int* __restrict__ x, const float* __restrict__ trans) {
    int b = blockIdx.x;
    int tag = threadIdx.x;
    __shared__ float st[NT * NT];
    __shared__ float ss[NT];
    for (int i = tag; i < NT * NT; i += 32) st[i] = trans[i];

    int len = 0;
    for (int t = tag; t < Tq; t += 32) len += (x[b * Tq + t] > 0) ? 1 : 0;
#pragma unroll
    for (int o = 16; o; o >>= 1) len += __shfl_xor_sync(0xffffffffu, len, o);

    float sc = (tag == 1) ? 0.0f : NEGV;
    ss[tag] = sc;
    __syncwarp();

    for (int t = 0; t < len; t++) {
        float emit = g_y[((size_t)t * Bq + b) * NT + tag];
        float mx = -3.4e38f;
#pragma unroll
        for (int p = 0; p < NT; p++) {
            float v = ss[p] + st[tag * NT + p];
            mx = fmaxf(mx, v);
        }
        float sum = 0.0f;
#pragma unroll
        for (int p = 0; p < NT; p++)
            sum += __expf(ss[p] + st[tag * NT + p] - mx);
        sc = emit + mx + __logf(sum);
        __syncwarp();
        ss[tag] = sc;
        __syncwarp();
    }

    float mx = sc;
#pragma unroll
    for (int o = 16; o; o >>= 1) mx = fmaxf(mx, __shfl_xor_sync(0xffffffffu, mx, o));
    float z;
    if (len < Tq) {
        z = mx + __logf(32.0f);
    } else {
        float sum = __expf(sc - mx);
#pragma unroll
        for (int o = 16; o; o >>= 1) sum += __shfl_xor_sync(0xffffffffu, sum, o);
        z = mx + __logf(sum);
    }
    if (tag == 0) g_Z[b] = z;
}

__global__ void k_final(float* __restrict__ out) {
    float s = 0.0f;
    for (int b = 0; b < Bq; b++) s += g_Z[b] - g_gold[b];
    out[0] = s / (float)Bq;
}

// ---------------- host launcher ----------------
extern "C" void kernel_launch(void* const* d_in, const int* in_sizes, int n_in,
                              void* d_out, int out_size) {
    (void)in_sizes; (void)n_in; (void)out_size;
    const int*   x     = (const int*)d_in[0];
    const int*   y0    = (const int*)d_in[1];
    const float* embw  = (const float*)d_in[2];
    const float* Wih0  = (const float*)d_in[3];
    const float* Whh0  = (const float*)d_in[4];
    const float* bih0  = (const float*)d_in[5];
    const float* bhh0  = (const float*)d_in[6];
    const float* Wih1  = (const float*)d_in[7];
    const float* Whh1  = (const float*)d_in[8];
    const float* bih1  = (const float*)d_in[9];
    const float* bhh1  = (const float*)d_in[10];
    const float* W_out = (const float*)d_in[11];
    const float* b_out = (const float*)d_in[12];
    const float* trans = (const float*)d_in[13];
    const float* h0    = (const float*)d_in[14];
    const float* c0    = (const float*)d_in[15];
    float* out = (float*)d_out;

    const int lstm_smem = (32000 + 4000 + 8 * SR_KS) * sizeof(float);  // ~163 KB
    cudaFuncSetAttribute(k_lstm, cudaFuncAttributeMaxDynamicSharedMemorySize, lstm_smem);

    k_embed<<<(Tq * Bq * Eq + 255) / 256, 256>>>(x, embw);

    {
        dim3 grid((G4 + 63) / 64, (Tq * Bq) / 64, 2);
        k_gemm<<<grid, 256>>>(0, Wih0, bih0, bhh0);
    }

    k_reset<<<1, 256>>>();
    k_lstm<<<NBLK, RTHR, lstm_smem>>>(0, Whh0, h0, c0, x);

    {
        dim3 grid((G4 + 63) / 64, (Tq * Bq) / 64, 2);
        k_gemm<<<grid, 256>>>(1, Wih1, bih1, bhh1);
    }

    k_reset<<<1, 256>>>();
    k_lstm<<<NBLK, RTHR, lstm_smem>>>(1, Whh1, h0, c0, x);

    k_outproj<<<(Tq * Bq) / 8, 256>>>(W_out, b_out);

    k_gold<<<Bq, 256>>>(x, y0, trans);
    k_crf<<<Bq, 32>>>(x, trans);
    k_final<<<1, 1>>>(out);
}

// round 13
// speedup vs baseline: 1.0252x; 1.0252x over previous
#include <cuda_runtime.h>
#include <math.h>
#include <stdint.h>

#define Bq 16
#define Tq 512
#define Eq 100
#define Hq 500
#define G4 2000
#define NT 32
#define NEGV (-10000.0f)

#define NBLK 128
#define RTHR 128
#define GRPSZ 32

// sred padded strides (floats)
#define SR_B 68
#define SR_KS 548

// GEMM tile
#define GTM 128
#define GTN 128

typedef unsigned long long ull;

// ---------------- device scratch ----------------
__device__ float g_xs[Tq * Bq * Eq];
__device__ float g_A0[2u * Tq * Bq * G4];
__device__ float g_A1[2u * Tq * Bq * G4];
__device__ float g_out0[Tq * Bq * 2 * Hq];
__device__ float g_out1[Tq * Bq * 2 * Hq];
__device__ float g_y[Tq * Bq * NT];
__device__ float g_hbuf[2 * 2 * Bq * 512];   // [d][pp][b][512]
__device__ float g_gold[Bq];
__device__ float g_Z[Bq];
__device__ unsigned g_cnt[4 * 32];           // per-group counters, 128B apart

// ---------------- helpers ----------------
__device__ __forceinline__ float sigm_f(float v) {
    return __fdividef(1.0f, 1.0f + __expf(-v));
}
__device__ __forceinline__ float tanh_f(float v) {
    return 1.0f - __fdividef(2.0f, __expf(2.0f * v) + 1.0f);
}
__device__ __forceinline__ ull fma2(ull a, ull b, ull c) {
    ull d;
    asm("fma.rn.f32x2 %0, %1, %2, %3;" : "=l"(d) : "l"(a), "l"(b), "l"(c));
    return d;
}
__device__ __forceinline__ ull pk2(float a, float b) {
    ull r;
    asm("mov.b64 %0, {%1, %2};" : "=l"(r) : "f"(a), "f"(b));
    return r;
}
__device__ __forceinline__ float2 up2(ull v) {
    float2 r;
    asm("mov.b64 {%0, %1}, %2;" : "=f"(r.x), "=f"(r.y) : "l"(v));
    return r;
}
__device__ __forceinline__ void red_release_add1(unsigned* p) {
    asm volatile("red.release.gpu.global.add.u32 [%0], 1;" :: "l"(p) : "memory");
}
__device__ __forceinline__ unsigned ld_acquire(const unsigned* p) {
    unsigned v;
    asm volatile("ld.acquire.gpu.global.u32 %0, [%1];" : "=r"(v) : "l"(p) : "memory");
    return v;
}

__global__ void k_reset() {
    if (threadIdx.x < 4 * 32) g_cnt[threadIdx.x] = 0u;
}

// ---------------- embedding ----------------
__global__ void k_embed(const int* __restrict__ x, const float* __restrict__ embw) {
    int idx = blockIdx.x * blockDim.x + threadIdx.x;
    if (idx >= Tq * Bq * Eq) return;
    int e = idx % Eq;
    int rb = idx / Eq;
    int b = rb % Bq;
    int t = rb / Bq;
    int row = x[b * Tq + t];
    g_xs[idx] = embw[(size_t)row * Eq + e];
}

// ---------------- 128x128 fp32 GEMM, 8x8 thread tile, FFMA2, double-buffered ----------------
// C[d][M,N] = X[M,K] @ W[d][N,K]^T + b1[d] + b2[d]
__global__ __launch_bounds__(256) void k_gemm(int lay,
                                              const float* __restrict__ W,
                                              const float* __restrict__ b1,
                                              const float* __restrict__ b2) {
    const int M = Tq * Bq;
    const int N = G4;
    const int K = (lay == 0) ? Eq : (2 * Hq);
    const float* X = (lay == 0) ? g_xs : g_out0;
    float* C = (lay == 0) ? g_A0 : g_A1;

    __shared__ ull sX[2][8][GTM];   // [buf][kpair][m] packed f32x2 along K
    __shared__ ull sW[2][8][GTN];   // [buf][kpair][n]

    int d = blockIdx.z;
    const float* Wd = W + (size_t)d * N * K;
    const float* b1d = b1 + (size_t)d * N;
    const float* b2d = b2 + (size_t)d * N;
    float* Cd = C + (size_t)d * M * N;

    int m0 = blockIdx.y * GTM, n0 = blockIdx.x * GTN;
    int tid = threadIdx.x;
    int lr = tid >> 1;          // 0..127 (row within tile)
    int lh = tid & 1;           // k-offset 8*lh within 16-wide ktile
    int tx = tid & 15, ty = tid >> 4;

    ull acc[8][8];
#pragma unroll
    for (int i = 0; i < 8; i++)
#pragma unroll
        for (int j = 0; j < 8; j++) acc[i][j] = 0ull;

    const int nt = (K + 15) / 16;
    const float4 f4z = make_float4(0.f, 0.f, 0.f, 0.f);

    const float* Xrow = &X[(size_t)(m0 + lr) * K];
    bool wok = (n0 + lr) < N;
    const float* Wrow = &Wd[(size_t)(wok ? (n0 + lr) : 0) * K];

    // prologue: tile 0
    {
        int kt = lh * 8;
        float4 xa = (kt < K) ? *(const float4*)&Xrow[kt] : f4z;
        float4 xb = (kt + 4 < K) ? *(const float4*)&Xrow[kt + 4] : f4z;
        float4 wa = (wok && kt < K) ? *(const float4*)&Wrow[kt] : f4z;
        float4 wb = (wok && kt + 4 < K) ? *(const float4*)&Wrow[kt + 4] : f4z;
        sX[0][lh * 4 + 0][lr] = pk2(xa.x, xa.y);
        sX[0][lh * 4 + 1][lr] = pk2(xa.z, xa.w);
        sX[0][lh * 4 + 2][lr] = pk2(xb.x, xb.y);
        sX[0][lh * 4 + 3][lr] = pk2(xb.z, xb.w);
        sW[0][lh * 4 + 0][lr] = pk2(wa.x, wa.y);
        sW[0][lh * 4 + 1][lr] = pk2(wa.z, wa.w);
        sW[0][lh * 4 + 2][lr] = pk2(wb.x, wb.y);
        sW[0][lh * 4 + 3][lr] = pk2(wb.z, wb.w);
    }
    __syncthreads();

    for (int ti = 0; ti < nt; ti++) {
        int cur = ti & 1;
        // prefetch next tile (global -> regs) overlapped with compute
        float4 nxa = f4z, nxb = f4z, nwa = f4z, nwb = f4z;
        if (ti + 1 < nt) {
            int kt = (ti + 1) * 16 + lh * 8;
            if (kt < K)      nxa = *(const float4*)&Xrow[kt];
            if (kt + 4 < K)  nxb = *(const float4*)&Xrow[kt + 4];
            if (wok && kt < K)     nwa = *(const float4*)&Wrow[kt];
            if (wok && kt + 4 < K) nwb = *(const float4*)&Wrow[kt + 4];
        }
#pragma unroll
        for (int kp = 0; kp < 8; kp++) {
            ulonglong2 xm0 = *(const ulonglong2*)&sX[cur][kp][ty * 8 + 0];
            ulonglong2 xm1 = *(const ulonglong2*)&sX[cur][kp][ty * 8 + 2];
            ulonglong2 xm2 = *(const ulonglong2*)&sX[cur][kp][ty * 8 + 4];
            ulonglong2 xm3 = *(const ulonglong2*)&sX[cur][kp][ty * 8 + 6];
            ulonglong2 wn0 = *(const ulonglong2*)&sW[cur][kp][tx * 8 + 0];
            ulonglong2 wn1 = *(const ulonglong2*)&sW[cur][kp][tx * 8 + 2];
            ulonglong2 wn2 = *(const ulonglong2*)&sW[cur][kp][tx * 8 + 4];
            ulonglong2 wn3 = *(const ulonglong2*)&sW[cur][kp][tx * 8 + 6];
            ull xr[8] = {xm0.x, xm0.y, xm1.x, xm1.y, xm2.x, xm2.y, xm3.x, xm3.y};
            ull wr[8] = {wn0.x, wn0.y, wn1.x, wn1.y, wn2.x, wn2.y, wn3.x, wn3.y};
#pragma unroll
            for (int i = 0; i < 8; i++)
#pragma unroll
                for (int j = 0; j < 8; j++)
                    acc[i][j] = fma2(xr[i], wr[j], acc[i][j]);
        }
        if (ti + 1 < nt) {
            int nb = (ti + 1) & 1;
            sX[nb][lh * 4 + 0][lr] = pk2(nxa.x, nxa.y);
            sX[nb][lh * 4 + 1][lr] = pk2(nxa.z, nxa.w);
            sX[nb][lh * 4 + 2][lr] = pk2(nxb.x, nxb.y);
            sX[nb][lh * 4 + 3][lr] = pk2(nxb.z, nxb.w);
            sW[nb][lh * 4 + 0][lr] = pk2(nwa.x, nwa.y);
            sW[nb][lh * 4 + 1][lr] = pk2(nwa.z, nwa.w);
            sW[nb][lh * 4 + 2][lr] = pk2(nwb.x, nwb.y);
            sW[nb][lh * 4 + 3][lr] = pk2(nwb.z, nwb.w);
            __syncthreads();
        }
    }

    // epilogue: N divisible by 8 -> whole 8-col chunks valid or not
    int c0 = n0 + tx * 8;
    if (c0 < N) {
        float bsum[8];
#pragma unroll
        for (int j = 0; j < 8; j++) bsum[j] = b1d[c0 + j] + b2d[c0 + j];
#pragma unroll
        for (int i = 0; i < 8; i++) {
            int row = m0 + ty * 8 + i;
            float r[8];
#pragma unroll
            for (int j = 0; j < 8; j++) {
                float2 p = up2(acc[i][j]);
                r[j] = p.x + p.y + bsum[j];
            }
            *(float4*)&Cd[(size_t)row * N + c0]     = make_float4(r[0], r[1], r[2], r[3]);
            *(float4*)&Cd[(size_t)row * N + c0 + 4] = make_float4(r[4], r[5], r[6], r[7]);
        }
    }
}

// ---------------- persistent bidirectional LSTM, register-tiled ----------------
// 128 blocks = (2 dirs) x (2 b-groups of 8) x (32 j-groups of 16).
// 128 threads = 8 K-splits x (2 b-subgroups x 8 j-subgroups).
// Sync: R11-style group counter (release-add / all-thread acquire-poll).
__device__ __forceinline__ void gbar_all(unsigned* cnt, unsigned want) {
    __syncthreads();
    if (threadIdx.x == 0) red_release_add1(cnt);
    unsigned ns = 20;
    while (ld_acquire(cnt) < want) {
        __nanosleep(ns);
        if (ns < 160) ns += ns;
    }
}

__global__ __launch_bounds__(RTHR, 1) void k_lstm(int lay,
                                                  const float* __restrict__ Whh,
                                                  const float* __restrict__ h0,
                                                  const float* __restrict__ c0,
                                                  const int* __restrict__ x) {
    extern __shared__ float sm[];
    float* sW = sm;            // [g][jl][i] : 4*16*500 = 32000 floats (128 KB)
    float* sh = sm + 32000;    // [bl][i]    : 8*500    = 4000 floats  (16 KB)
    float* sred = sm + 36000;  // [ks][b][j][g] padded : 8*548 = 4384 floats

    const float* A = (lay == 0) ? g_A0 : g_A1;
    float* outp = (lay == 0) ? g_out0 : g_out1;
    const int hbase = lay * 2;

    int tid = threadIdx.x;
    // dot role
    int ks = tid >> 4;          // 0..7
    int cell = tid & 15;
    int bg_t = cell & 1;
    int jg_t = cell >> 1;
    // owner role
    int obl = tid & 7;
    int ojl = tid >> 3;

    int bx = blockIdx.x;
    int d = bx >> 6;
    int rem = bx & 63;
    int bg = rem >> 5;
    int jg = rem & 31;
    int b0 = bg * 8;
    int j0 = jg * 16;
    int oj = j0 + ojl;
    int ob = b0 + obl;
    bool jok = (oj < Hq);
    unsigned* cnt = &g_cnt[(d * 2 + bg) * 32];

    // load Whh slice: sW[(g*16+jl2)*500 + i]
    for (int idx = tid; idx < 32000; idx += RTHR) {
        int g = idx / 8000;
        int r = idx % 8000;
        int jl2 = r / 500;
        int i = r % 500;
        int jc = j0 + jl2;
        sW[idx] = (jc < Hq) ? Whh[((size_t)d * G4 + g * Hq + jc) * Hq + i] : 0.0f;
    }

    float hreg = jok ? h0[((size_t)(hbase + d) * Bq + ob) * Hq + oj] : 0.0f;
    float creg = jok ? c0[((size_t)(hbase + d) * Bq + ob) * Hq + oj] : 0.0f;
    g_hbuf[((d * 2 + 0) * Bq + ob) * 512 + oj] = hreg;
    unsigned bs = 1;
    gbar_all(cnt, GRPSZ * bs); bs++;

    const float* Ad = A + (size_t)d * Tq * Bq * G4;

    // K-slice for this thread: chunks of 4 floats (ulonglong2), 125 total
    int cb = ks * 15 + (ks < 5 ? ks : 5);
    int cn = (ks < 5) ? 16 : 15;

    // smem row pointers
    const ulonglong2* hrow[4];
#pragma unroll
    for (int bi = 0; bi < 4; bi++)
        hrow[bi] = (const ulonglong2*)&sh[(bg_t * 4 + bi) * 500];
    const ulonglong2* wrow[2][4];
#pragma unroll
    for (int ji = 0; ji < 2; ji++)
#pragma unroll
        for (int g = 0; g < 4; g++)
            wrow[ji][g] = (const ulonglong2*)&sW[(g * 16 + jg_t * 2 + ji) * 500];

    // A-prefetch for step 0
    float ag0, ag1, ag2, ag3;
    int xv;
    {
        int t0 = d ? (Tq - 1) : 0;
        size_t arow = ((size_t)t0 * Bq + ob) * G4 + (jok ? oj : 0);
        ag0 = __ldg(&Ad[arow + 0 * Hq]);
        ag1 = __ldg(&Ad[arow + 1 * Hq]);
        ag2 = __ldg(&Ad[arow + 2 * Hq]);
        ag3 = __ldg(&Ad[arow + 3 * Hq]);
        xv = __ldg(&x[ob * Tq + t0]);
    }

    int pp = 0;
    for (int s = 0; s < Tq; s++) {
        int t = d ? (Tq - 1 - s) : s;

        // stage h for this block's 8 batch rows: exactly 8*125 = 1000 float4
        for (int q = tid; q < 1000; q += RTHR) {
            int bb = q / 125;
            int i4 = q - bb * 125;
            float4 v = __ldcg((const float4*)&g_hbuf[((d * 2 + pp) * Bq + b0 + bb) * 512 + i4 * 4]);
            *(float4*)&sh[bb * 500 + i4 * 4] = v;
        }
        __syncthreads();

        // prefetch NEXT step's gate pre-activations + mask (hidden under the dot)
        float ng0 = 0.f, ng1 = 0.f, ng2 = 0.f, ng3 = 0.f;
        int nxv = 0;
        if (s + 1 < Tq) {
            int tn = d ? (Tq - 2 - s) : (s + 1);
            size_t arown = ((size_t)tn * Bq + ob) * G4 + (jok ? oj : 0);
            ng0 = __ldg(&Ad[arown + 0 * Hq]);
            ng1 = __ldg(&Ad[arown + 1 * Hq]);
            ng2 = __ldg(&Ad[arown + 2 * Hq]);
            ng3 = __ldg(&Ad[arown + 3 * Hq]);
            nxv = __ldg(&x[ob * Tq + tn]);
        }

        // register-tiled dot: acc[bi][ji][g]
        ull acc[4][2][4];
#pragma unroll
        for (int bi = 0; bi < 4; bi++)
#pragma unroll
            for (int ji = 0; ji < 2; ji++)
#pragma unroll
                for (int g = 0; g < 4; g++) acc[bi][ji][g] = 0ull;

#pragma unroll 2
        for (int ii = cb; ii < cb + cn; ii++) {
            ulonglong2 hv[4];
#pragma unroll
            for (int bi = 0; bi < 4; bi++) hv[bi] = hrow[bi][ii];
            ulonglong2 wv[2][4];
#pragma unroll
            for (int ji = 0; ji < 2; ji++)
#pragma unroll
                for (int g = 0; g < 4; g++) wv[ji][g] = wrow[ji][g][ii];
#pragma unroll
            for (int bi = 0; bi < 4; bi++)
#pragma unroll
                for (int ji = 0; ji < 2; ji++)
#pragma unroll
                    for (int g = 0; g < 4; g++) {
                        acc[bi][ji][g] = fma2(hv[bi].x, wv[ji][g].x, acc[bi][ji][g]);
                        acc[bi][ji][g] = fma2(hv[bi].y, wv[ji][g].y, acc[bi][ji][g]);
                    }
        }

        // write partials to sred[ks][b][j][g] (padded)
#pragma unroll
        for (int bi = 0; bi < 4; bi++)
#pragma unroll
            for (int ji = 0; ji < 2; ji++)
#pragma unroll
                for (int g = 0; g < 4; g++) {
                    float2 p = up2(acc[bi][ji][g]);
                    sred[ks * SR_KS + (bg_t * 4 + bi) * SR_B + (jg_t * 2 + ji) * 4 + g] = p.x + p.y;
                }
        __syncthreads();

        // owner: reduce 8 K-partials per gate, nonlinearity, state update
        {
            int base = obl * SR_B + ojl * 4;
            float gi = ag0, gf = ag1, gg = ag2, go = ag3;
#pragma unroll
            for (int k = 0; k < 8; k++) {
                const float* r = &sred[k * SR_KS + base];
                gi += r[0]; gf += r[1]; gg += r[2]; go += r[3];
            }

            float cn2 = sigm_f(gf) * creg + sigm_f(gi) * tanh_f(gg);
            float hn = sigm_f(go) * tanh_f(cn2);

            bool m = xv > 0;
            if (jok)
                outp[((size_t)t * Bq + ob) * (2 * Hq) + d * Hq + oj] = m ? hn : 0.0f;
            if (m) { creg = cn2; hreg = hn; }

            g_hbuf[((d * 2 + (pp ^ 1)) * Bq + ob) * 512 + oj] = hreg;
        }
        gbar_all(cnt, GRPSZ * bs); bs++;
        pp ^= 1;
        ag0 = ng0; ag1 = ng1; ag2 = ng2; ag3 = ng3; xv = nxv;
    }
}

// ---------------- output projection ----------------
__global__ __launch_bounds__(256) void k_outproj(const float* __restrict__ Wo,
                                                 const float* __restrict__ bo) {
    int r0 = blockIdx.x * 8;
    int tag = threadIdx.x & 31;
    int part = threadIdx.x >> 5;
    float acc[8];
#pragma unroll
    for (int r = 0; r < 8; r++) acc[r] = 0.0f;

    const float* w = Wo + (size_t)tag * 1000 + part * 125;
    for (int i = 0; i < 125; i++) {
        float wv = __ldg(&w[i]);
        int col = part * 125 + i;
#pragma unroll
        for (int r = 0; r < 8; r++)
            acc[r] = fmaf(wv, g_out1[(size_t)(r0 + r) * 1000 + col], acc[r]);
    }

    __shared__ float red[8][8][32];
#pragma unroll
    for (int r = 0; r < 8; r++) red[part][r][tag] = acc[r];
    __syncthreads();
    if (part == 0) {
#pragma unroll
        for (int r = 0; r < 8; r++) {
            float s = bo[tag];
#pragma unroll
            for (int p = 0; p < 8; p++) s += red[p][r][tag];
            g_y[(size_t)(r0 + r) * NT + tag] = s;
        }
    }
}

// ---------------- gold path score ----------------
__global__ void k_gold(const int* __restrict__ x, const int* __restrict__ y0,
                       const float* __restrict__ trans) {
    int b = blockIdx.x;
    float s = 0.0f;
    for (int t = threadIdx.x; t < Tq; t += blockDim.x) {
        if (x[b * Tq + t] > 0) {
            int cur = y0[b * Tq + t];
            int prev = (t == 0) ? 1 : y0[b * Tq + t - 1];
            s += g_y[((size_t)t * Bq + b) * NT + cur] + trans[cur * NT + prev];
        }
    }
    __shared__ float red[256];
    red[threadIdx.x] = s;
    __syncthreads();
    for (int k = 128; k > 0; k >>= 1) {
        if (threadIdx.x < k) red[threadIdx.x] += red[threadIdx.x + k];
        __syncthreads();
    }
    if (threadIdx.x == 0) g_gold[b] = red[0];
}

// ---------------- CRF forward ----------------
__global__ void k_crf(const int* __restrict__ x, const float* __restrict__ trans) {
    int b = blockIdx.x;
    int tag = threadIdx.x;
    __shared__ float st[NT * NT];
    __shared__ float ss[NT];
    for (int i = tag; i < NT * NT; i += 32) st[i] = trans[i];

    int len = 0;
    for (int t = tag; t < Tq; t += 32) len += (x[b * Tq + t] > 0) ? 1 : 0;
#pragma unroll
    for (int o = 16; o; o >>= 1) len += __shfl_xor_sync(0xffffffffu, len, o);

    float sc = (tag == 1) ? 0.0f : NEGV;
    ss[tag] = sc;
    __syncwarp();

    for (int t = 0; t < len; t++) {
        float emit = g_y[((size_t)t * Bq + b) * NT + tag];
        float mx = -3.4e38f;
#pragma unroll
        for (int p = 0; p < NT; p++) {
            float v = ss[p] + st[tag * NT + p];
            mx = fmaxf(mx, v);
        }
        float sum = 0.0f;
#pragma unroll
        for (int p = 0; p < NT; p++)
            sum += __expf(ss[p] + st[tag * NT + p] - mx);
        sc = emit + mx + __logf(sum);
        __syncwarp();
        ss[tag] = sc;
        __syncwarp();
    }

    float mx = sc;
#pragma unroll
    for (int o = 16; o; o >>= 1) mx = fmaxf(mx, __shfl_xor_sync(0xffffffffu, mx, o));
    float z;
    if (len < Tq) {
        z = mx + __logf(32.0f);
    } else {
        float sum = __expf(sc - mx);
#pragma unroll
        for (int o = 16; o; o >>= 1) sum += __shfl_xor_sync(0xffffffffu, sum, o);
        z = mx + __logf(sum);
    }
    if (tag == 0) g_Z[b] = z;
}

__global__ void k_final(float* __restrict__ out) {
    float s = 0.0f;
    for (int b = 0; b < Bq; b++) s += g_Z[b] - g_gold[b];
    out[0] = s / (float)Bq;
}

// ---------------- host launcher ----------------
extern "C" void kernel_launch(void* const* d_in, const int* in_sizes, int n_in,
                              void* d_out, int out_size) {
    (void)in_sizes; (void)n_in; (void)out_size;
    const int*   x     = (const int*)d_in[0];
    const int*   y0    = (const int*)d_in[1];
    const float* embw  = (const float*)d_in[2];
    const float* Wih0  = (const float*)d_in[3];
    const float* Whh0  = (const float*)d_in[4];
    const float* bih0  = (const float*)d_in[5];
    const float* bhh0  = (const float*)d_in[6];
    const float* Wih1  = (const float*)d_in[7];
    const float* Whh1  = (const float*)d_in[8];
    const float* bih1  = (const float*)d_in[9];
    const float* bhh1  = (const float*)d_in[10];
    const float* W_out = (const float*)d_in[11];
    const float* b_out = (const float*)d_in[12];
    const float* trans = (const float*)d_in[13];
    const float* h0    = (const float*)d_in[14];
    const float* c0    = (const float*)d_in[15];
    float* out = (float*)d_out;

    const int lstm_smem = (32000 + 4000 + 8 * SR_KS) * sizeof(float);  // ~163 KB
    cudaFuncSetAttribute(k_lstm, cudaFuncAttributeMaxDynamicSharedMemorySize, lstm_smem);

    k_embed<<<(Tq * Bq * Eq + 255) / 256, 256>>>(x, embw);

    {
        dim3 grid((G4 + GTN - 1) / GTN, (Tq * Bq) / GTM, 2);
        k_gemm<<<grid, 256>>>(0, Wih0, bih0, bhh0);
    }

    k_reset<<<1, 128>>>();
    k_lstm<<<NBLK, RTHR, lstm_smem>>>(0, Whh0, h0, c0, x);

    {
        dim3 grid((G4 + GTN - 1) / GTN, (Tq * Bq) / GTM, 2);
        k_gemm<<<grid, 256>>>(1, Wih1, bih1, bhh1);
    }

    k_reset<<<1, 128>>>();
    k_lstm<<<NBLK, RTHR, lstm_smem>>>(1, Whh1, h0, c0, x);

    k_outproj<<<(Tq * Bq) / 8, 256>>>(W_out, b_out);

    k_gold<<<Bq, 256>>>(x, y0, trans);
    k_crf<<<Bq, 32>>>(x, trans);
    k_final<<<1, 1>>>(out);
}